// round 5
// baseline (speedup 1.0000x reference)
#include <cuda_runtime.h>
#include <math_constants.h>

// Output = one-hot(argmax over F of logits+gumbel); forward-exact vs reference
// (straight-through mask is numerically one-hot; the top-K-smallest zeroing
//  only touches entries that are already exactly 0).
//
// R5: two adjacent rows per warp, software-pipelined. Row r+1's 8 LDG.128s
// are issued after row r's sums are folded into (best,bidx) but BEFORE row
// r's shuffle reduction + store, so the warp always has loads in flight
// during its non-load phases. Peak live payload ~= one row (32 regs) ->
// stays in the 40-warp/SM register tier.

static constexpr int Bc = 32;
static constexpr int Sc = 2048;
static constexpr int Fc = 512;
static constexpr int ROWS = Bc * Sc;          // 65536 rows
static constexpr int F4  = Fc / 4;            // 128 float4 per row

struct Payload { float4 a0, a1, a2, a3, g0, g1, g2, g3; };

__device__ __forceinline__ void load_row(const float4* __restrict__ lp,
                                         const float4* __restrict__ gp,
                                         Payload& p) {
    p.a0 = lp[0];  p.a1 = lp[32]; p.a2 = lp[64]; p.a3 = lp[96];
    p.g0 = gp[0];  p.g1 = gp[32]; p.g2 = gp[64]; p.g3 = gp[96];
}

// Fold one row's payload into (best, bidx). Indices strictly increase within
// a lane, so strict ">" gives the first-index tie-break per lane.
__device__ __forceinline__ void fold_row(const Payload& p, int lane,
                                         float& best, int& bidx) {
    best = -CUDART_INF_F; bidx = 0;
    float s; int e;
    e = (0 * 32 + lane) * 4;
    s = p.a0.x + p.g0.x; if (s > best) { best = s; bidx = e;     }
    s = p.a0.y + p.g0.y; if (s > best) { best = s; bidx = e + 1; }
    s = p.a0.z + p.g0.z; if (s > best) { best = s; bidx = e + 2; }
    s = p.a0.w + p.g0.w; if (s > best) { best = s; bidx = e + 3; }
    e = (1 * 32 + lane) * 4;
    s = p.a1.x + p.g1.x; if (s > best) { best = s; bidx = e;     }
    s = p.a1.y + p.g1.y; if (s > best) { best = s; bidx = e + 1; }
    s = p.a1.z + p.g1.z; if (s > best) { best = s; bidx = e + 2; }
    s = p.a1.w + p.g1.w; if (s > best) { best = s; bidx = e + 3; }
    e = (2 * 32 + lane) * 4;
    s = p.a2.x + p.g2.x; if (s > best) { best = s; bidx = e;     }
    s = p.a2.y + p.g2.y; if (s > best) { best = s; bidx = e + 1; }
    s = p.a2.z + p.g2.z; if (s > best) { best = s; bidx = e + 2; }
    s = p.a2.w + p.g2.w; if (s > best) { best = s; bidx = e + 3; }
    e = (3 * 32 + lane) * 4;
    s = p.a3.x + p.g3.x; if (s > best) { best = s; bidx = e;     }
    s = p.a3.y + p.g3.y; if (s > best) { best = s; bidx = e + 1; }
    s = p.a3.z + p.g3.z; if (s > best) { best = s; bidx = e + 2; }
    s = p.a3.w + p.g3.w; if (s > best) { best = s; bidx = e + 3; }
}

// Butterfly: max by value, lowest index on ties (== jnp.argmax).
// Lexicographic max is associative+commutative -> all lanes converge.
__device__ __forceinline__ void reduce_warp(float& best, int& bidx) {
    #pragma unroll
    for (int off = 16; off; off >>= 1) {
        const float ov = __shfl_xor_sync(0xffffffffu, best, off);
        const int   oi = __shfl_xor_sync(0xffffffffu, bidx, off);
        if (ov > best || (ov == best && oi < bidx)) { best = ov; bidx = oi; }
    }
}

__device__ __forceinline__ void store_row(float4* __restrict__ op, int lane,
                                          int bidx) {
    #pragma unroll
    for (int c = 0; c < 4; c++) {
        const int e = (c * 32 + lane) * 4;
        float4 o;
        o.x = (e     == bidx) ? 1.0f : 0.0f;
        o.y = (e + 1 == bidx) ? 1.0f : 0.0f;
        o.z = (e + 2 == bidx) ? 1.0f : 0.0f;
        o.w = (e + 3 == bidx) ? 1.0f : 0.0f;
        op[c * 32] = o;
    }
}

__global__ __launch_bounds__(256)
void onehot_argmax_kernel(const float4* __restrict__ logits,
                          const float4* __restrict__ gumbel,
                          float4* __restrict__ out) {
    const int warp = (blockIdx.x * blockDim.x + threadIdx.x) >> 5;
    const int lane = threadIdx.x & 31;
    const int row0 = warp * 2;
    if (row0 >= ROWS) return;

    const size_t base0 = (size_t)row0 * F4;
    const size_t base1 = base0 + F4;

    // ---- pipeline ----
    Payload p0;
    load_row(logits + base0 + lane, gumbel + base0 + lane, p0);   // row0 loads

    float best0; int bidx0;
    fold_row(p0, lane, best0, bidx0);                             // frees p0 regs

    Payload p1;
    load_row(logits + base1 + lane, gumbel + base1 + lane, p1);   // row1 loads in flight...

    reduce_warp(best0, bidx0);                                    // ...during row0 reduce
    store_row(out + base0 + lane, lane, bidx0);                   // ...and row0 store

    float best1; int bidx1;
    fold_row(p1, lane, best1, bidx1);
    reduce_warp(best1, bidx1);
    store_row(out + base1 + lane, lane, bidx1);
}

extern "C" void kernel_launch(void* const* d_in, const int* in_sizes, int n_in,
                              void* d_out, int out_size) {
    const float4* logits = (const float4*)d_in[0];
    const float4* gumbel = (const float4*)d_in[1];
    float4* out = (float4*)d_out;

    const int threads = 256;
    const int rows_per_block = (threads / 32) * 2;                // 16
    const int blocks = ROWS / rows_per_block;                     // 4096
    onehot_argmax_kernel<<<blocks, threads>>>(logits, gumbel, out);
}

// round 6
// speedup vs baseline: 1.0221x; 1.0221x over previous
#include <cuda_runtime.h>
#include <math_constants.h>

// FINAL (R1 config — measured best: 52.2us kernel, DRAM 84.6%, 6701 GB/s).
//
// Output = one-hot(argmax over F of logits+gumbel); forward-exact vs reference:
//   * straight-through mask (y_hard - sg(y_soft) + y_soft) is numerically
//     exact 0 off-argmax and ~1 (within 2^-24) at the argmax;
//   * softmax is monotone, so argmax(softmax((l+g)/tau)) = argmax(l+g);
//   * the top-K-smallest-then-zero step only selects entries that are already
//     exactly 0 (K=104857 << 1046528 zeros per batch) -> no-op.
//
// HBM-bound streaming kernel: 256 MiB read + 128 MiB write = 384 MiB floor.
// One warp per row, 8 LDG.128 per warp, butterfly argmax, STG.128 one-hot.
// R2-R5 established that occupancy/persistence/MLP restructuring cannot move
// the 6.6-6.7 TB/s plateau (memory-controller read/write turnaround bound).

static constexpr int Bc = 32;
static constexpr int Sc = 2048;
static constexpr int Fc = 512;
static constexpr int ROWS = Bc * Sc;          // 65536 rows
static constexpr int F4  = Fc / 4;            // 128 float4 per row

__global__ __launch_bounds__(256)
void onehot_argmax_kernel(const float4* __restrict__ logits,
                          const float4* __restrict__ gumbel,
                          float4* __restrict__ out) {
    const int warp = (blockIdx.x * blockDim.x + threadIdx.x) >> 5;
    const int lane = threadIdx.x & 31;
    if (warp >= ROWS) return;

    const size_t base = (size_t)warp * F4;

    float best = -CUDART_INF_F;
    int   bidx = 0;

    // Each lane handles 4 float4s: positions c*32 + lane (c = 0..3).
    // Indices strictly increase within a lane, so strict ">" gives the
    // first-index tie-break per lane; cross-lane tie-break in the butterfly.
    #pragma unroll
    for (int c = 0; c < 4; c++) {
        const int p = c * 32 + lane;
        const float4 a = logits[base + p];
        const float4 g = gumbel[base + p];
        const float s0 = a.x + g.x;
        const float s1 = a.y + g.y;
        const float s2 = a.z + g.z;
        const float s3 = a.w + g.w;
        const int e = p * 4;
        if (s0 > best) { best = s0; bidx = e;     }
        if (s1 > best) { best = s1; bidx = e + 1; }
        if (s2 > best) { best = s2; bidx = e + 2; }
        if (s3 > best) { best = s3; bidx = e + 3; }
    }

    // Butterfly reduction: max by value, lowest index on ties (== jnp.argmax).
    // Lexicographic max is associative+commutative, so every lane converges to
    // the row argmax — no broadcast needed before the store phase.
    #pragma unroll
    for (int off = 16; off; off >>= 1) {
        const float ov = __shfl_xor_sync(0xffffffffu, best, off);
        const int   oi = __shfl_xor_sync(0xffffffffu, bidx, off);
        if (ov > best || (ov == best && oi < bidx)) { best = ov; bidx = oi; }
    }

    // Compose + write the one-hot row (each lane owns its float4s; no RMW).
    #pragma unroll
    for (int c = 0; c < 4; c++) {
        const int p = c * 32 + lane;
        const int e = p * 4;
        float4 o;
        o.x = (e     == bidx) ? 1.0f : 0.0f;
        o.y = (e + 1 == bidx) ? 1.0f : 0.0f;
        o.z = (e + 2 == bidx) ? 1.0f : 0.0f;
        o.w = (e + 3 == bidx) ? 1.0f : 0.0f;
        out[base + p] = o;
    }
}

extern "C" void kernel_launch(void* const* d_in, const int* in_sizes, int n_in,
                              void* d_out, int out_size) {
    const float4* logits = (const float4*)d_in[0];
    const float4* gumbel = (const float4*)d_in[1];
    float4* out = (float4*)d_out;

    const int threads = 256;
    const int warps_per_block = threads / 32;
    const int blocks = (ROWS + warps_per_block - 1) / warps_per_block;  // 8192
    onehot_argmax_kernel<<<blocks, threads>>>(logits, gumbel, out);
}